// round 12
// baseline (speedup 1.0000x reference)
#include <cuda_runtime.h>
#include <cuda_fp16.h>
#include <mma.h>
#include <cstddef>
#include <cstdint>

using namespace nvcuda;

#define B 16
#define S 1024
#define D 384
#define QK 64

__device__ __half g_Qh[(size_t)B * S * QK];
__device__ __half g_Kh[(size_t)B * S * QK];
__device__ __half g_Xh[(size_t)B * S * D];    // x in fp16, natural [b][m][c]
__device__ __half g_Ph[(size_t)B * S * S];    // softmax probs fp16

#define CP_ASYNC16(dst_u32, src_ptr) \
    asm volatile("cp.async.cg.shared.global [%0], [%1], 16;\n" :: "r"(dst_u32), "l"(src_ptr))
#define CP_COMMIT() asm volatile("cp.async.commit_group;\n" ::)
#define CP_WAIT2()  asm volatile("cp.async.wait_group 2;\n" ::)
#define CP_WAIT1()  asm volatile("cp.async.wait_group 1;\n" ::)
#define CP_WAIT0()  asm volatile("cp.async.wait_group 0;\n" ::)

#define PITCH 72                      // fp16 smem pitch for 64-col tiles (144B)
#define BPITCH16 136                  // fp16 smem pitch for 128-col tiles (272B)
#define KMAT_BYTES (128 * PITCH * 2)  // 18432
#define SPITCH 132

typedef wmma::fragment<wmma::matrix_a, 16, 16, 16, __half, wmma::row_major> FragA;
typedef wmma::fragment<wmma::matrix_b, 16, 16, 16, __half, wmma::col_major> FragB;
typedef wmma::fragment<wmma::matrix_b, 16, 16, 16, __half, wmma::row_major> FragBR;
typedef wmma::fragment<wmma::accumulator, 16, 16, 16, float> FragC;

typedef wmma::fragment<wmma::matrix_a, 16, 16, 8, wmma::precision::tf32, wmma::row_major> TFragA;
typedef wmma::fragment<wmma::matrix_b, 16, 16, 8, wmma::precision::tf32, wmma::col_major> TFragB;
typedef wmma::fragment<wmma::accumulator, 16, 16, 8, float> TFragC;

// ---------------------------------------------------------------------------
// Kernel 1: proj via tf32 wmma (unchanged).
// ---------------------------------------------------------------------------
#define APITCH 392
#define WPITCH 72
#define PROJ_SMEM (16*APITCH*4 + 2*128*WPITCH*4 + 16*132*4)

__global__ __launch_bounds__(256) void proj_mma(
    const float* __restrict__ x, const float* __restrict__ qw,
    const float* __restrict__ qb, const float* __restrict__ kw)
{
    extern __shared__ float psm[];
    float* As    = psm;                      // 16 x 392
    float* Bs    = psm + 16 * APITCH;        // 2 x 128 x 72
    float* stage = Bs + 2 * 128 * WPITCH;    // 16 x 132

    const int n = blockIdx.x;
    const int tid = threadIdx.x;
    const uint32_t smA = (uint32_t)__cvta_generic_to_shared(As);
    const uint32_t smB = (uint32_t)__cvta_generic_to_shared(Bs);

    const float* xp = x + (size_t)n * D;
    #pragma unroll
    for (int i = 0; i < 6; i++) {
        int g = tid + 256 * i;
        int r = g / 96, c = g % 96;
        CP_ASYNC16(smA + (uint32_t)(r * APITCH + c * 4) * 4u,
                   xp + (size_t)r * S * D + c * 4);
    }

    #define LOAD_W(kc_, buf_) do { \
        const uint32_t bb_ = smB + (uint32_t)(buf_) * (128u * WPITCH * 4u); \
        _Pragma("unroll") \
        for (int i = 0; i < 8; i++) { \
            int g = tid + 256 * i; \
            int r = g >> 4, c = g & 15; \
            const float* src_ = (r < 64) \
                ? (qw + ((size_t)n * QK + r) * D) \
                : (kw + ((size_t)n * QK + (r - 64)) * D); \
            CP_ASYNC16(bb_ + (uint32_t)(r * WPITCH + c * 4) * 4u, \
                       src_ + (kc_) * 64 + c * 4); \
        } \
    } while (0)

    LOAD_W(0, 0); CP_COMMIT();
    LOAD_W(1, 1); CP_COMMIT();

    const int wid = tid >> 5;
    TFragC cacc;
    wmma::fill_fragment(cacc, 0.0f);

    for (int kc = 0; kc < 6; kc++) {
        if (kc < 5) CP_WAIT1(); else CP_WAIT0();
        __syncthreads();

        const float* buf = Bs + (size_t)(kc & 1) * 128 * WPITCH;
        #pragma unroll
        for (int ks = 0; ks < 8; ks++) {
            TFragA a;
            TFragB bfr;
            wmma::load_matrix_sync(a, As + kc * 64 + ks * 8, APITCH);
            wmma::load_matrix_sync(bfr, buf + (size_t)(wid * 16) * WPITCH + ks * 8, WPITCH);
            #pragma unroll
            for (int t = 0; t < a.num_elements; t++) a.x[t] = wmma::__float_to_tf32(a.x[t]);
            #pragma unroll
            for (int t = 0; t < bfr.num_elements; t++) bfr.x[t] = wmma::__float_to_tf32(bfr.x[t]);
            wmma::mma_sync(cacc, a, bfr, cacc);
        }
        __syncthreads();
        if (kc + 2 < 6) { LOAD_W(kc + 2, kc & 1); CP_COMMIT(); }
    }

    wmma::store_matrix_sync(stage + wid * 16, cacc, 132, wmma::mem_row_major);
    __syncthreads();

    const float scale = 0.05103103630798287f;
    #pragma unroll
    for (int i = 0; i < 8; i++) {
        int g = tid + 256 * i;
        int b = g >> 7, d = g & 127;
        float v = stage[b * 132 + d];
        if (d < QK)
            g_Qh[((size_t)b * S + n) * QK + d] = __float2half_rn(scale * (v + qb[n * QK + d]));
        else
            g_Kh[((size_t)b * S + n) * QK + (d - QK)] = __float2half_rn(v);
    }
    #undef LOAD_W
}

// ---------------------------------------------------------------------------
// Kernel 1b: fp32 -> fp16 convert of x
// ---------------------------------------------------------------------------
__global__ __launch_bounds__(256) void xconv_kernel(const float* __restrict__ x)
{
    const size_t base = ((size_t)blockIdx.x * 256 + threadIdx.x) * 8;
    float4 v0 = *(const float4*)(x + base);
    float4 v1 = *(const float4*)(x + base + 4);
    __half2 h0 = __floats2half2_rn(v0.x, v0.y);
    __half2 h1 = __floats2half2_rn(v0.z, v0.w);
    __half2 h2 = __floats2half2_rn(v1.x, v1.y);
    __half2 h3 = __floats2half2_rn(v1.z, v1.w);
    uint4 o;
    o.x = *(uint32_t*)&h0; o.y = *(uint32_t*)&h1;
    o.z = *(uint32_t*)&h2; o.w = *(uint32_t*)&h3;
    *(uint4*)&g_Xh[base] = o;
}

// ---------------------------------------------------------------------------
// Kernel 2: logits + TWO-PASS fused softmax (no raw-logit gmem round-trip).
// Grid=256 (b, nt of 64 rows), 128 thr (4 warps).
// Pass 0: stream K tiles, compute 64x128 logit tiles into smem stage,
//         online per-row max/sum (warp-local; warp w owns row w+4*i).
// Pass 1: re-stream K, recompute tiles, write softmaxed attn fp32 + P fp16.
// smem: Q 9216 + 3*18432 K + stage 64*132*4 + state 512 = 98816.
// ---------------------------------------------------------------------------
__global__ __launch_bounds__(128) void logits_mma(
    const float* __restrict__ attn_bias, float* __restrict__ attn)
{
    extern __shared__ __half sm[];
    __half* Qh = sm;                                 // 64 x 72
    float* stage  = (float*)(sm + 4608 + 3 * 128 * PITCH);   // 64 x 132 fp32
    float* rowmx  = stage + 64 * SPITCH;             // 64
    float* rowsum = rowmx + 64;                      // 64

    const int tid = threadIdx.x;
    const int bx = blockIdx.x;
    const int nt = bx & 15, b = bx >> 4;
    const int n0 = nt * 64;

    const uint32_t smb = (uint32_t)__cvta_generic_to_shared(sm);
    const __half* qhp = g_Qh + ((size_t)b * S + n0) * QK;
    const __half* khp = g_Kh + (size_t)b * S * QK;

    #define LOAD_K(mt_, bufj_) do { \
        const uint32_t kb_ = smb + 9216u + (uint32_t)(bufj_) * KMAT_BYTES; \
        const __half* kh_ = khp + (size_t)(mt_) * 128 * QK; \
        _Pragma("unroll") \
        for (int i = 0; i < 8; i++) { \
            int g = tid + 128 * i; \
            int r = g >> 3, c16 = g & 7; \
            CP_ASYNC16(kb_ + (uint32_t)(r * 144 + c16 * 16), kh_ + (size_t)r * QK + c16 * 8); \
        } \
    } while (0)

    // Q (part of pass-0 group 0)
    #pragma unroll
    for (int i = 0; i < 4; i++) {
        int g = tid + 128 * i;
        int r = g >> 3, c16 = g & 7;
        CP_ASYNC16(smb + (uint32_t)(r * 144 + c16 * 16), qhp + (size_t)r * QK + c16 * 8);
    }

    if (tid < 64) { rowmx[tid] = -1e30f; rowsum[tid] = 0.0f; }

    const int wid = tid >> 5;
    const int lane = tid & 31;

    for (int pass = 0; pass < 2; pass++) {
        __syncthreads();
        LOAD_K(0, 0); CP_COMMIT();
        LOAD_K(1, 1); CP_COMMIT();

        for (int mt = 0; mt < 8; mt++) {
            if (mt + 2 < 8) { LOAD_K(mt + 2, (mt + 2) % 3); CP_COMMIT(); }
            if (mt < 6)       CP_WAIT2();
            else if (mt == 6) CP_WAIT1();
            else              CP_WAIT0();
            __syncthreads();

            const __half* Kh = sm + 4608 + (size_t)(mt % 3) * 128 * PITCH;
            const int m0 = mt * 128;

            FragC acc[4][2];
            #pragma unroll
            for (int i = 0; i < 4; i++)
                #pragma unroll
                for (int j = 0; j < 2; j++) wmma::fill_fragment(acc[i][j], 0.0f);

            #pragma unroll
            for (int kk = 0; kk < 4; kk++) {
                FragA ah[4];
                FragB bh[2];
                #pragma unroll
                for (int i = 0; i < 4; i++)
                    wmma::load_matrix_sync(ah[i], Qh + (i * 16) * PITCH + kk * 16, PITCH);
                #pragma unroll
                for (int j = 0; j < 2; j++)
                    wmma::load_matrix_sync(bh[j], Kh + (wid * 32 + j * 16) * PITCH + kk * 16, PITCH);
                #pragma unroll
                for (int i = 0; i < 4; i++)
                    #pragma unroll
                    for (int j = 0; j < 2; j++)
                        wmma::mma_sync(acc[i][j], ah[i], bh[j], acc[i][j]);
            }

            #pragma unroll
            for (int i = 0; i < 4; i++)
                #pragma unroll
                for (int j = 0; j < 2; j++)
                    wmma::store_matrix_sync(
                        stage + (size_t)(i * 16) * SPITCH + wid * 32 + j * 16,
                        acc[i][j], SPITCH, wmma::mem_row_major);
            __syncthreads();

            if (pass == 0) {
                // online max/sum: warp w owns row w + 4*i2, 32 lanes = 32 f4 cols
                #pragma unroll
                for (int i2 = 0; i2 < 16; i2++) {
                    const int r = wid + 4 * i2;
                    float4 v = *(float4*)&stage[(size_t)r * SPITCH + lane * 4];
                    float4 bb = __ldg((const float4*)&attn_bias[(size_t)(n0 + r) * S + m0 + lane * 4]);
                    v.x += bb.x; v.y += bb.y; v.z += bb.z; v.w += bb.w;

                    float tm = fmaxf(fmaxf(v.x, v.y), fmaxf(v.z, v.w));
                    #pragma unroll
                    for (int o = 16; o > 0; o >>= 1)
                        tm = fmaxf(tm, __shfl_xor_sync(0xffffffffu, tm, o));

                    const float old = rowmx[r];
                    const float nm = fmaxf(old, tm);
                    float es = __expf(v.x - nm) + __expf(v.y - nm)
                             + __expf(v.z - nm) + __expf(v.w - nm);
                    #pragma unroll
                    for (int o = 16; o > 0; o >>= 1)
                        es += __shfl_xor_sync(0xffffffffu, es, o);
                    if (lane == 0) {
                        rowsum[r] = rowsum[r] * __expf(old - nm) + es;
                        rowmx[r] = nm;
                    }
                }
            } else {
                #pragma unroll
                for (int i2 = 0; i2 < 16; i2++) {
                    const int r = wid + 4 * i2;
                    float4 v = *(float4*)&stage[(size_t)r * SPITCH + lane * 4];
                    float4 bb = __ldg((const float4*)&attn_bias[(size_t)(n0 + r) * S + m0 + lane * 4]);
                    const float m = rowmx[r];
                    const float inv = rowsum[r];   // 1/sum after inversion
                    float p0 = __expf(v.x + bb.x - m) * inv;
                    float p1 = __expf(v.y + bb.y - m) * inv;
                    float p2 = __expf(v.z + bb.z - m) * inv;
                    float p3 = __expf(v.w + bb.w - m) * inv;
                    float4 o4 = {p0, p1, p2, p3};
                    *(float4*)&attn[((size_t)b * S + n0 + r) * S + m0 + lane * 4] = o4;
                    __half h0 = __float2half_rn(p0), h1 = __float2half_rn(p1);
                    __half h2 = __float2half_rn(p2), h3 = __float2half_rn(p3);
                    unsigned u0 = (unsigned)__half_as_ushort(h0) | ((unsigned)__half_as_ushort(h1) << 16);
                    unsigned u1 = (unsigned)__half_as_ushort(h2) | ((unsigned)__half_as_ushort(h3) << 16);
                    *(uint2*)&g_Ph[((size_t)b * S + n0 + r) * S + m0 + lane * 4] = make_uint2(u0, u1);
                }
            }
            __syncthreads();   // stage + K-buffer reuse
        }

        if (pass == 0) {
            if (tid < 64) rowsum[tid] = 1.0f / rowsum[tid];
        }
    }
    #undef LOAD_K
}

// ---------------------------------------------------------------------------
// Kernel 4: out = P @ x (unchanged from R11).
// ---------------------------------------------------------------------------
#define OBUF_BYTES 35840
#define OBUF_HALF  17920

__global__ __launch_bounds__(128) void out_mma(float* __restrict__ out)
{
    extern __shared__ __half sm[];

    const int tid = threadIdx.x;
    const int bx = blockIdx.x;
    const int ct = bx % 3;
    const int nt = (bx / 3) & 7;
    const int b  = bx / 24;
    const int n0 = nt * 128, c0 = ct * 128;

    const uint32_t smb = (uint32_t)__cvta_generic_to_shared(sm);
    const __half* aHp = g_Ph + ((size_t)b * S + n0) * S;
    const __half* xp  = g_Xh + (size_t)b * S * D;

    const int wid = tid >> 5;
    const int wn = wid >> 1;
    const int wc = wid & 1;

    #define LOAD_CHUNK(kc_, bufj_) do { \
        const int kof_ = (kc_) * 64; \
        const uint32_t ab_ = smb + (uint32_t)(bufj_) * OBUF_BYTES; \
        const uint32_t xb_ = ab_ + 18432u; \
        _Pragma("unroll") \
        for (int i = 0; i < 8; i++) { \
            int g = tid + 128 * i; \
            int r = g >> 3, c16 = g & 7; \
            CP_ASYNC16(ab_ + (uint32_t)(r * 144 + c16 * 16), \
                       aHp + (size_t)r * S + kof_ + c16 * 8); \
        } \
        _Pragma("unroll") \
        for (int i = 0; i < 8; i++) { \
            int g = tid + 128 * i; \
            int r = g >> 4, c16 = g & 15; \
            CP_ASYNC16(xb_ + (uint32_t)(r * 272 + c16 * 16), \
                       xp + (size_t)(kof_ + r) * D + c0 + c16 * 8); \
        } \
    } while (0)

    LOAD_CHUNK(0, 0); CP_COMMIT();

    FragC acc[4][4];
    #pragma unroll
    for (int i = 0; i < 4; i++)
        #pragma unroll
        for (int j = 0; j < 4; j++) wmma::fill_fragment(acc[i][j], 0.0f);

    for (int kc = 0; kc < 16; kc++) {
        if (kc < 15) { LOAD_CHUNK(kc + 1, (kc + 1) & 1); CP_COMMIT(); CP_WAIT1(); }
        else         { CP_WAIT0(); }
        __syncthreads();

        const __half* Ah = sm + (size_t)(kc & 1) * OBUF_HALF;
        const __half* Bh = Ah + 9216;

        #pragma unroll
        for (int kk = 0; kk < 4; kk++) {
            FragA ah[4];
            FragBR bh[4];
            #pragma unroll
            for (int i = 0; i < 4; i++)
                wmma::load_matrix_sync(ah[i], Ah + (wn * 64 + i * 16) * PITCH + kk * 16, PITCH);
            #pragma unroll
            for (int j = 0; j < 4; j++)
                wmma::load_matrix_sync(bh[j], Bh + (kk * 16) * BPITCH16 + wc * 64 + j * 16, BPITCH16);
            #pragma unroll
            for (int i = 0; i < 4; i++)
                #pragma unroll
                for (int j = 0; j < 4; j++)
                    wmma::mma_sync(acc[i][j], ah[i], bh[j], acc[i][j]);
        }
        __syncthreads();
    }

    #pragma unroll
    for (int i = 0; i < 4; i++) {
        const int row = n0 + wn * 64 + i * 16;
        #pragma unroll
        for (int j = 0; j < 4; j++) {
            const int col = c0 + wc * 64 + j * 16;
            wmma::store_matrix_sync(out + ((size_t)b * S + row) * D + col,
                                    acc[i][j], D, wmma::mem_row_major);
        }
    }
    #undef LOAD_CHUNK
}

// ---------------------------------------------------------------------------
extern "C" void kernel_launch(void* const* d_in, const int* in_sizes, int n_in,
                              void* d_out, int out_size)
{
    const float* x         = (const float*)d_in[0];
    const float* q_weight  = (const float*)d_in[1];
    const float* q_bias    = (const float*)d_in[2];
    const float* k_weight  = (const float*)d_in[3];
    const float* attn_bias = (const float*)d_in[4];

    float* out  = (float*)d_out;                       // [B,S,D]
    float* attn = (float*)d_out + (size_t)B * S * D;   // [B,S,S]

    cudaFuncSetAttribute(proj_mma,   cudaFuncAttributeMaxDynamicSharedMemorySize, PROJ_SMEM);
    cudaFuncSetAttribute(logits_mma, cudaFuncAttributeMaxDynamicSharedMemorySize, 98816);
    cudaFuncSetAttribute(out_mma,    cudaFuncAttributeMaxDynamicSharedMemorySize, 71680);

    proj_mma<<<S, 256, PROJ_SMEM>>>(x, q_weight, q_bias, k_weight);

    xconv_kernel<<<(B * S * D) / (256 * 8), 256>>>(x);

    logits_mma<<<256, 128, 98816>>>(attn_bias, attn);

    out_mma<<<384, 128, 71680>>>(out);
}

// round 13
// speedup vs baseline: 1.3825x; 1.3825x over previous
#include <cuda_runtime.h>
#include <cuda_fp16.h>
#include <mma.h>
#include <cstddef>
#include <cstdint>

using namespace nvcuda;

#define B 16
#define S 1024
#define D 384
#define QK 64

__device__ __half g_Qh[(size_t)B * S * QK];
__device__ __half g_Kh[(size_t)B * S * QK];
__device__ __half g_Xh[(size_t)B * S * D];    // x in fp16, natural [b][m][c]
__device__ __half g_Ph[(size_t)B * S * S];    // softmax probs fp16

#define CP_ASYNC16(dst_u32, src_ptr) \
    asm volatile("cp.async.cg.shared.global [%0], [%1], 16;\n" :: "r"(dst_u32), "l"(src_ptr))
#define CP_COMMIT() asm volatile("cp.async.commit_group;\n" ::)
#define CP_WAIT2()  asm volatile("cp.async.wait_group 2;\n" ::)
#define CP_WAIT1()  asm volatile("cp.async.wait_group 1;\n" ::)
#define CP_WAIT0()  asm volatile("cp.async.wait_group 0;\n" ::)

#define PITCH 72                      // fp16 smem pitch for 64-col tiles (144B)
#define BPITCH16 136                  // fp16 smem pitch for 128-col tiles (272B)
#define KMAT_BYTES (128 * PITCH * 2)  // 18432
#define SPITCH 132

typedef wmma::fragment<wmma::matrix_a, 16, 16, 16, __half, wmma::row_major> FragA;
typedef wmma::fragment<wmma::matrix_b, 16, 16, 16, __half, wmma::col_major> FragB;
typedef wmma::fragment<wmma::matrix_b, 16, 16, 16, __half, wmma::row_major> FragBR;
typedef wmma::fragment<wmma::accumulator, 16, 16, 16, float> FragC;

typedef wmma::fragment<wmma::matrix_a, 16, 16, 8, wmma::precision::tf32, wmma::row_major> TFragA;
typedef wmma::fragment<wmma::matrix_b, 16, 16, 8, wmma::precision::tf32, wmma::col_major> TFragB;
typedef wmma::fragment<wmma::accumulator, 16, 16, 8, float> TFragC;

// ---------------------------------------------------------------------------
// Kernel 1: proj via tf32 wmma (unchanged).
// ---------------------------------------------------------------------------
#define APITCH 392
#define WPITCH 72
#define PROJ_SMEM (16*APITCH*4 + 2*128*WPITCH*4 + 16*132*4)

__global__ __launch_bounds__(256) void proj_mma(
    const float* __restrict__ x, const float* __restrict__ qw,
    const float* __restrict__ qb, const float* __restrict__ kw)
{
    extern __shared__ float psm[];
    float* As    = psm;                      // 16 x 392
    float* Bs    = psm + 16 * APITCH;        // 2 x 128 x 72
    float* stage = Bs + 2 * 128 * WPITCH;    // 16 x 132

    const int n = blockIdx.x;
    const int tid = threadIdx.x;
    const uint32_t smA = (uint32_t)__cvta_generic_to_shared(As);
    const uint32_t smB = (uint32_t)__cvta_generic_to_shared(Bs);

    const float* xp = x + (size_t)n * D;
    #pragma unroll
    for (int i = 0; i < 6; i++) {
        int g = tid + 256 * i;
        int r = g / 96, c = g % 96;
        CP_ASYNC16(smA + (uint32_t)(r * APITCH + c * 4) * 4u,
                   xp + (size_t)r * S * D + c * 4);
    }

    #define LOAD_W(kc_, buf_) do { \
        const uint32_t bb_ = smB + (uint32_t)(buf_) * (128u * WPITCH * 4u); \
        _Pragma("unroll") \
        for (int i = 0; i < 8; i++) { \
            int g = tid + 256 * i; \
            int r = g >> 4, c = g & 15; \
            const float* src_ = (r < 64) \
                ? (qw + ((size_t)n * QK + r) * D) \
                : (kw + ((size_t)n * QK + (r - 64)) * D); \
            CP_ASYNC16(bb_ + (uint32_t)(r * WPITCH + c * 4) * 4u, \
                       src_ + (kc_) * 64 + c * 4); \
        } \
    } while (0)

    LOAD_W(0, 0); CP_COMMIT();
    LOAD_W(1, 1); CP_COMMIT();

    const int wid = tid >> 5;
    TFragC cacc;
    wmma::fill_fragment(cacc, 0.0f);

    for (int kc = 0; kc < 6; kc++) {
        if (kc < 5) CP_WAIT1(); else CP_WAIT0();
        __syncthreads();

        const float* buf = Bs + (size_t)(kc & 1) * 128 * WPITCH;
        #pragma unroll
        for (int ks = 0; ks < 8; ks++) {
            TFragA a;
            TFragB bfr;
            wmma::load_matrix_sync(a, As + kc * 64 + ks * 8, APITCH);
            wmma::load_matrix_sync(bfr, buf + (size_t)(wid * 16) * WPITCH + ks * 8, WPITCH);
            #pragma unroll
            for (int t = 0; t < a.num_elements; t++) a.x[t] = wmma::__float_to_tf32(a.x[t]);
            #pragma unroll
            for (int t = 0; t < bfr.num_elements; t++) bfr.x[t] = wmma::__float_to_tf32(bfr.x[t]);
            wmma::mma_sync(cacc, a, bfr, cacc);
        }
        __syncthreads();
        if (kc + 2 < 6) { LOAD_W(kc + 2, kc & 1); CP_COMMIT(); }
    }

    wmma::store_matrix_sync(stage + wid * 16, cacc, 132, wmma::mem_row_major);
    __syncthreads();

    const float scale = 0.05103103630798287f;
    #pragma unroll
    for (int i = 0; i < 8; i++) {
        int g = tid + 256 * i;
        int b = g >> 7, d = g & 127;
        float v = stage[b * 132 + d];
        if (d < QK)
            g_Qh[((size_t)b * S + n) * QK + d] = __float2half_rn(scale * (v + qb[n * QK + d]));
        else
            g_Kh[((size_t)b * S + n) * QK + (d - QK)] = __float2half_rn(v);
    }
    #undef LOAD_W
}

// ---------------------------------------------------------------------------
// Kernel 1b: fp32 -> fp16 convert of x
// ---------------------------------------------------------------------------
__global__ __launch_bounds__(256) void xconv_kernel(const float* __restrict__ x)
{
    const size_t base = ((size_t)blockIdx.x * 256 + threadIdx.x) * 8;
    float4 v0 = *(const float4*)(x + base);
    float4 v1 = *(const float4*)(x + base + 4);
    __half2 h0 = __floats2half2_rn(v0.x, v0.y);
    __half2 h1 = __floats2half2_rn(v0.z, v0.w);
    __half2 h2 = __floats2half2_rn(v1.x, v1.y);
    __half2 h3 = __floats2half2_rn(v1.z, v1.w);
    uint4 o;
    o.x = *(uint32_t*)&h0; o.y = *(uint32_t*)&h1;
    o.z = *(uint32_t*)&h2; o.w = *(uint32_t*)&h3;
    *(uint4*)&g_Xh[base] = o;
}

// ---------------------------------------------------------------------------
// Kernel 2: logits + fused softmax (R11 single-pass algorithm), 256 threads
// (8 warps, warp tile 32n x 32m) for 2x issue parallelism.
// Grid=256 (b, nt of 64 rows), 2 CTA/SM.
// smem: Q 9216 + 3*18432 K + stage 64*132*4 = 98304.
// ---------------------------------------------------------------------------
__global__ __launch_bounds__(256) void logits_mma(
    const float* __restrict__ attn_bias, float* __restrict__ attn)
{
    extern __shared__ __half sm[];
    __half* Qh = sm;                                  // 64 x 72
    float* stage = (float*)(sm + 4608 + 3 * 128 * PITCH);  // 64 x 132 fp32

    const int tid = threadIdx.x;
    const int bx = blockIdx.x;
    const int nt = bx & 15, b = bx >> 4;
    const int n0 = nt * 64;

    const uint32_t smb = (uint32_t)__cvta_generic_to_shared(sm);
    const __half* qhp = g_Qh + ((size_t)b * S + n0) * QK;
    const __half* khp = g_Kh + (size_t)b * S * QK;

    #define LOAD_K(mt_, bufj_) do { \
        const uint32_t kb_ = smb + 9216u + (uint32_t)(bufj_) * KMAT_BYTES; \
        const __half* kh_ = khp + (size_t)(mt_) * 128 * QK; \
        _Pragma("unroll") \
        for (int i = 0; i < 4; i++) { \
            int g = tid + 256 * i; \
            int r = g >> 3, c16 = g & 7; \
            CP_ASYNC16(kb_ + (uint32_t)(r * 144 + c16 * 16), kh_ + (size_t)r * QK + c16 * 8); \
        } \
    } while (0)

    // Q: 64 rows x 8 chunks = 512
    #pragma unroll
    for (int i = 0; i < 2; i++) {
        int g = tid + 256 * i;
        int r = g >> 3, c16 = g & 7;
        CP_ASYNC16(smb + (uint32_t)(r * 144 + c16 * 16), qhp + (size_t)r * QK + c16 * 8);
    }
    LOAD_K(0, 0); CP_COMMIT();
    LOAD_K(1, 1); CP_COMMIT();

    const int wid = tid >> 5;     // 0..7
    const int lane = tid & 31;
    const int wn = wid >> 2;      // 0..1 -> 32 rows
    const int wm = wid & 3;       // 0..3 -> 32 cols

    for (int mt = 0; mt < 8; mt++) {
        __syncthreads();
        if (mt + 2 < 8) { LOAD_K(mt + 2, (mt + 2) % 3); CP_COMMIT(); }
        if (mt < 6)       CP_WAIT2();
        else if (mt == 6) CP_WAIT1();
        else              CP_WAIT0();
        __syncthreads();

        const __half* Kh = sm + 4608 + (size_t)(mt % 3) * 128 * PITCH;
        const int m0 = mt * 128;

        FragC acc[2][2];
        #pragma unroll
        for (int i = 0; i < 2; i++)
            #pragma unroll
            for (int j = 0; j < 2; j++) wmma::fill_fragment(acc[i][j], 0.0f);

        #pragma unroll
        for (int kk = 0; kk < 4; kk++) {
            FragA ah[2];
            FragB bh[2];
            #pragma unroll
            for (int i = 0; i < 2; i++)
                wmma::load_matrix_sync(ah[i], Qh + (wn * 32 + i * 16) * PITCH + kk * 16, PITCH);
            #pragma unroll
            for (int j = 0; j < 2; j++)
                wmma::load_matrix_sync(bh[j], Kh + (wm * 32 + j * 16) * PITCH + kk * 16, PITCH);
            #pragma unroll
            for (int i = 0; i < 2; i++)
                #pragma unroll
                for (int j = 0; j < 2; j++)
                    wmma::mma_sync(acc[i][j], ah[i], bh[j], acc[i][j]);
        }

        #pragma unroll
        for (int i = 0; i < 2; i++)
            #pragma unroll
            for (int j = 0; j < 2; j++)
                wmma::store_matrix_sync(
                    stage + (size_t)(wn * 32 + i * 16) * SPITCH + wm * 32 + j * 16,
                    acc[i][j], SPITCH, wmma::mem_row_major);
        __syncthreads();

        // coalesced bias add + raw-logit store: 64 rows x 32 float4 = 2048
        #pragma unroll
        for (int i = 0; i < 8; i++) {
            int g = tid + 256 * i;
            int r = g >> 5, c4 = (g & 31) * 4;
            float4 v = *(float4*)&stage[(size_t)r * SPITCH + c4];
            float4 bb = __ldg((const float4*)&attn_bias[(size_t)(n0 + r) * S + m0 + c4]);
            v.x += bb.x; v.y += bb.y; v.z += bb.z; v.w += bb.w;
            *(float4*)&attn[((size_t)b * S + n0 + r) * S + m0 + c4] = v;
        }
    }

    // fused softmax: 8 warps x 8 rows
    __syncthreads();
    #pragma unroll 1
    for (int rr = 0; rr < 8; rr++) {
        const int r = wid * 8 + rr;
        float* rowp = attn + ((size_t)b * S + n0 + r) * S;
        __half* php = g_Ph + ((size_t)b * S + n0 + r) * S;

        float4 v[8];
        #pragma unroll
        for (int j = 0; j < 8; j++)
            v[j] = *(float4*)&rowp[j * 128 + lane * 4];

        float mx = -1e30f;
        #pragma unroll
        for (int j = 0; j < 8; j++)
            mx = fmaxf(mx, fmaxf(fmaxf(v[j].x, v[j].y), fmaxf(v[j].z, v[j].w)));
        #pragma unroll
        for (int o = 16; o > 0; o >>= 1) mx = fmaxf(mx, __shfl_xor_sync(0xffffffffu, mx, o));

        float ssum = 0.f;
        #pragma unroll
        for (int j = 0; j < 8; j++) {
            v[j].x = __expf(v[j].x - mx); v[j].y = __expf(v[j].y - mx);
            v[j].z = __expf(v[j].z - mx); v[j].w = __expf(v[j].w - mx);
            ssum += (v[j].x + v[j].y) + (v[j].z + v[j].w);
        }
        #pragma unroll
        for (int o = 16; o > 0; o >>= 1) ssum += __shfl_xor_sync(0xffffffffu, ssum, o);
        const float inv = 1.0f / ssum;

        #pragma unroll
        for (int j = 0; j < 8; j++) {
            float p0 = v[j].x * inv, p1 = v[j].y * inv;
            float p2 = v[j].z * inv, p3 = v[j].w * inv;
            float4 o4 = {p0, p1, p2, p3};
            *(float4*)&rowp[j * 128 + lane * 4] = o4;
            __half h0 = __float2half_rn(p0), h1 = __float2half_rn(p1);
            __half h2 = __float2half_rn(p2), h3 = __float2half_rn(p3);
            unsigned u0 = (unsigned)__half_as_ushort(h0) | ((unsigned)__half_as_ushort(h1) << 16);
            unsigned u1 = (unsigned)__half_as_ushort(h2) | ((unsigned)__half_as_ushort(h3) << 16);
            *(uint2*)&php[j * 128 + lane * 4] = make_uint2(u0, u1);
        }
    }
    #undef LOAD_K
}

// ---------------------------------------------------------------------------
// Kernel 4: out = P @ x (unchanged from R11).
// ---------------------------------------------------------------------------
#define OBUF_BYTES 35840
#define OBUF_HALF  17920

__global__ __launch_bounds__(128) void out_mma(float* __restrict__ out)
{
    extern __shared__ __half sm[];

    const int tid = threadIdx.x;
    const int bx = blockIdx.x;
    const int ct = bx % 3;
    const int nt = (bx / 3) & 7;
    const int b  = bx / 24;
    const int n0 = nt * 128, c0 = ct * 128;

    const uint32_t smb = (uint32_t)__cvta_generic_to_shared(sm);
    const __half* aHp = g_Ph + ((size_t)b * S + n0) * S;
    const __half* xp  = g_Xh + (size_t)b * S * D;

    const int wid = tid >> 5;
    const int wn = wid >> 1;
    const int wc = wid & 1;

    #define LOAD_CHUNK(kc_, bufj_) do { \
        const int kof_ = (kc_) * 64; \
        const uint32_t ab_ = smb + (uint32_t)(bufj_) * OBUF_BYTES; \
        const uint32_t xb_ = ab_ + 18432u; \
        _Pragma("unroll") \
        for (int i = 0; i < 8; i++) { \
            int g = tid + 128 * i; \
            int r = g >> 3, c16 = g & 7; \
            CP_ASYNC16(ab_ + (uint32_t)(r * 144 + c16 * 16), \
                       aHp + (size_t)r * S + kof_ + c16 * 8); \
        } \
        _Pragma("unroll") \
        for (int i = 0; i < 8; i++) { \
            int g = tid + 128 * i; \
            int r = g >> 4, c16 = g & 15; \
            CP_ASYNC16(xb_ + (uint32_t)(r * 272 + c16 * 16), \
                       xp + (size_t)(kof_ + r) * D + c0 + c16 * 8); \
        } \
    } while (0)

    LOAD_CHUNK(0, 0); CP_COMMIT();

    FragC acc[4][4];
    #pragma unroll
    for (int i = 0; i < 4; i++)
        #pragma unroll
        for (int j = 0; j < 4; j++) wmma::fill_fragment(acc[i][j], 0.0f);

    for (int kc = 0; kc < 16; kc++) {
        if (kc < 15) { LOAD_CHUNK(kc + 1, (kc + 1) & 1); CP_COMMIT(); CP_WAIT1(); }
        else         { CP_WAIT0(); }
        __syncthreads();

        const __half* Ah = sm + (size_t)(kc & 1) * OBUF_HALF;
        const __half* Bh = Ah + 9216;

        #pragma unroll
        for (int kk = 0; kk < 4; kk++) {
            FragA ah[4];
            FragBR bh[4];
            #pragma unroll
            for (int i = 0; i < 4; i++)
                wmma::load_matrix_sync(ah[i], Ah + (wn * 64 + i * 16) * PITCH + kk * 16, PITCH);
            #pragma unroll
            for (int j = 0; j < 4; j++)
                wmma::load_matrix_sync(bh[j], Bh + (kk * 16) * BPITCH16 + wc * 64 + j * 16, BPITCH16);
            #pragma unroll
            for (int i = 0; i < 4; i++)
                #pragma unroll
                for (int j = 0; j < 4; j++)
                    wmma::mma_sync(acc[i][j], ah[i], bh[j], acc[i][j]);
        }
        __syncthreads();
    }

    #pragma unroll
    for (int i = 0; i < 4; i++) {
        const int row = n0 + wn * 64 + i * 16;
        #pragma unroll
        for (int j = 0; j < 4; j++) {
            const int col = c0 + wc * 64 + j * 16;
            wmma::store_matrix_sync(out + ((size_t)b * S + row) * D + col,
                                    acc[i][j], D, wmma::mem_row_major);
        }
    }
    #undef LOAD_CHUNK
}

// ---------------------------------------------------------------------------
extern "C" void kernel_launch(void* const* d_in, const int* in_sizes, int n_in,
                              void* d_out, int out_size)
{
    const float* x         = (const float*)d_in[0];
    const float* q_weight  = (const float*)d_in[1];
    const float* q_bias    = (const float*)d_in[2];
    const float* k_weight  = (const float*)d_in[3];
    const float* attn_bias = (const float*)d_in[4];

    float* out  = (float*)d_out;                       // [B,S,D]
    float* attn = (float*)d_out + (size_t)B * S * D;   // [B,S,S]

    cudaFuncSetAttribute(proj_mma,   cudaFuncAttributeMaxDynamicSharedMemorySize, PROJ_SMEM);
    cudaFuncSetAttribute(logits_mma, cudaFuncAttributeMaxDynamicSharedMemorySize, 98304);
    cudaFuncSetAttribute(out_mma,    cudaFuncAttributeMaxDynamicSharedMemorySize, 71680);

    proj_mma<<<S, 256, PROJ_SMEM>>>(x, q_weight, q_bias, k_weight);

    xconv_kernel<<<(B * S * D) / (256 * 8), 256>>>(x);

    logits_mma<<<256, 256, 98304>>>(attn_bias, attn);

    out_mma<<<384, 128, 71680>>>(out);
}